// round 13
// baseline (speedup 1.0000x reference)
#include <cuda_runtime.h>

// Problem constants (match reference)
#define B   16
#define LX  2048
#define LR  1024
#define D   768
#define T   (LX + LR + 3)   // 3075
#define D4  (D / 4)         // 192 float4 per row
#define RPB 4               // rows per CTA (B*T = 49200 divisible by 4)
#define TPB 256             // 8 warps -> up to 32 warps/SM at 4 CTAs
#define CPB (RPB * D4)      // 768 chunks per CTA
#define KPT (CPB / TPB)     // 3 chunks per thread

// out[b,t,:] =
//   t == 0                          : CLS
//   1 <= t <= lx[b]                 : X[b, t-1]
//   t == lx[b]+1                    : RING
//   lx[b]+2 <= t < lx[b]+2+lr[b]    : Xr[b, t-lx[b]-2]
//   t == lx[b]+lr[b]+2              : END
//   else                            : 0
//
// R13: write-THROUGH stores (st.global.wt). Rationale: in the steady-state
// graph-replay loop every replay inherits ~126MB of dirty output lines in
// L2 from the previous replay; incoming read misses must force writebacks
// before filling (the invariant ~5.4us wall-vs-ncu gap). .wt keeps output
// lines clean in L2 (data pushed to DRAM at store time), removing the
// deferred-writeback burst at the head of each replay. Reads stay streaming.

__device__ __forceinline__ void stg_wt(float4* p, float4 v) {
    asm volatile("st.global.wt.v4.f32 [%0], {%1,%2,%3,%4};"
                 :: "l"(p), "f"(v.x), "f"(v.y), "f"(v.z), "f"(v.w));
}

__global__ __launch_bounds__(TPB) void assemble_kernel(
    const float4* __restrict__ X,
    const float4* __restrict__ Xr,
    const float4* __restrict__ CLS,
    const float4* __restrict__ RING,
    const float4* __restrict__ END,
    const int*    __restrict__ lx,
    const int*    __restrict__ lr,
    float4*       __restrict__ out)
{
    const int  tid  = threadIdx.x;
    const long base = (long)blockIdx.x * CPB;    // first chunk of this CTA

    float4 v[KPT];

    #pragma unroll
    for (int k = 0; k < KPT; k++) {
        const int chunk = tid + k * TPB;          // 0..767
        const int rl    = chunk / D4;             // row within CTA (0..3)
        const int c     = chunk - rl * D4;        // 0..191
        const int row   = blockIdx.x * RPB + rl;
        const int b     = row / T;                // const-div -> mul/shift
        const int t     = row - b * T;

        const int lxb = __ldg(&lx[b]);
        const int lrb = __ldg(&lr[b]);

        if (t == 0) {
            v[k] = CLS[c];
        } else if (t <= lxb) {
            v[k] = __ldcs(&X[((long)b * LX + (t - 1)) * D4 + c]);
        } else if (t == lxb + 1) {
            v[k] = RING[c];
        } else if (t < lxb + 2 + lrb) {
            v[k] = __ldcs(&Xr[((long)b * LR + (t - lxb - 2)) * D4 + c]);
        } else if (t == lxb + lrb + 2) {
            v[k] = END[c];
        } else {
            v[k] = make_float4(0.f, 0.f, 0.f, 0.f);
        }
    }

    #pragma unroll
    for (int k = 0; k < KPT; k++) {
        stg_wt(&out[base + tid + k * TPB], v[k]);
    }
}

extern "C" void kernel_launch(void* const* d_in, const int* in_sizes, int n_in,
                              void* d_out, int out_size)
{
    const float4* X    = (const float4*)d_in[0];
    const float4* Xr   = (const float4*)d_in[1];
    const float4* CLS  = (const float4*)d_in[2];
    const float4* RING = (const float4*)d_in[3];
    const float4* END  = (const float4*)d_in[4];
    const int*    lx   = (const int*)d_in[5];
    const int*    lr   = (const int*)d_in[6];
    float4*       out  = (float4*)d_out;

    dim3 grid((B * T) / RPB);   // 12300 CTAs
    dim3 block(TPB);            // 256 threads
    assemble_kernel<<<grid, block>>>(X, Xr, CLS, RING, END, lx, lr, out);
}

// round 14
// speedup vs baseline: 1.0414x; 1.0414x over previous
#include <cuda_runtime.h>

// Problem constants (match reference)
#define B   16
#define LX  2048
#define LR  1024
#define D   768
#define T   (LX + LR + 3)   // 3075
#define D4  (D / 4)         // 192 float4 per row
#define RPB 8               // rows per CTA (B*T = 49200 divisible by 8)
#define TPB 512             // 16 warps; 4 CTAs/SM -> 2048 thr/SM at 22 regs
#define CPB (RPB * D4)      // 1536 chunks per CTA
#define KPT (CPB / TPB)     // 3 chunks per thread (register-light, unlike R9)

// out[b,t,:] =
//   t == 0                          : CLS
//   1 <= t <= lx[b]                 : X[b, t-1]
//   t == lx[b]+1                    : RING
//   lx[b]+2 <= t < lx[b]+2+lr[b]    : Xr[b, t-lx[b]-2]
//   t == lx[b]+lr[b]+2              : END
//   else                            : 0
//
// Measured-best policy: streaming on both sides (__ldcs/__stcs) — working
// set 226MB > 126MB L2, nothing retainable across graph replays.
// Structure: flat chunk indexing (R12 scheme) extended to 8 rows / 24KB
// contiguous span per CTA. KPT stays 3, so register pressure does NOT grow
// with RPB (R9's mistake). 192 % 32 == 0 -> each warp's 32 consecutive
// chunks sit in one row: warp-uniform branch, fully coalesced 128B accesses.
__global__ __launch_bounds__(TPB) void assemble_kernel(
    const float4* __restrict__ X,
    const float4* __restrict__ Xr,
    const float4* __restrict__ CLS,
    const float4* __restrict__ RING,
    const float4* __restrict__ END,
    const int*    __restrict__ lx,
    const int*    __restrict__ lr,
    float4*       __restrict__ out)
{
    const int  tid  = threadIdx.x;
    const long base = (long)blockIdx.x * CPB;    // first chunk of this CTA

    float4 v[KPT];

    #pragma unroll
    for (int k = 0; k < KPT; k++) {
        const int chunk = tid + k * TPB;          // 0..1535
        const int rl    = chunk / D4;             // row within CTA (0..7)
        const int c     = chunk - rl * D4;        // 0..191
        const int row   = blockIdx.x * RPB + rl;
        const int b     = row / T;                // const-div -> mul/shift
        const int t     = row - b * T;

        const int lxb = __ldg(&lx[b]);
        const int lrb = __ldg(&lr[b]);

        if (t == 0) {
            v[k] = CLS[c];
        } else if (t <= lxb) {
            v[k] = __ldcs(&X[((long)b * LX + (t - 1)) * D4 + c]);
        } else if (t == lxb + 1) {
            v[k] = RING[c];
        } else if (t < lxb + 2 + lrb) {
            v[k] = __ldcs(&Xr[((long)b * LR + (t - lxb - 2)) * D4 + c]);
        } else if (t == lxb + lrb + 2) {
            v[k] = END[c];
        } else {
            v[k] = make_float4(0.f, 0.f, 0.f, 0.f);
        }
    }

    #pragma unroll
    for (int k = 0; k < KPT; k++) {
        __stcs(&out[base + tid + k * TPB], v[k]);
    }
}

extern "C" void kernel_launch(void* const* d_in, const int* in_sizes, int n_in,
                              void* d_out, int out_size)
{
    const float4* X    = (const float4*)d_in[0];
    const float4* Xr   = (const float4*)d_in[1];
    const float4* CLS  = (const float4*)d_in[2];
    const float4* RING = (const float4*)d_in[3];
    const float4* END  = (const float4*)d_in[4];
    const int*    lx   = (const int*)d_in[5];
    const int*    lr   = (const int*)d_in[6];
    float4*       out  = (float4*)d_out;

    dim3 grid((B * T) / RPB);   // 6150 CTAs
    dim3 block(TPB);            // 512 threads
    assemble_kernel<<<grid, block>>>(X, Xr, CLS, RING, END, lx, lr, out);
}